// round 2
// baseline (speedup 1.0000x reference)
#include <cuda_runtime.h>
#include <math.h>

#define DIMK   256
#define LATENT 1024
#define BB     128
#define TT     512

// ---------------------------------------------------------------------------
// GEMM1: out[t, b, :] = x[b, t, :] @ Wx + bias   (M=B*T=65536, K=256, N=1024)
// Row r = b*T + t. Classic SGEMM: BM=64, BN=64, BK=16, 256 threads, 4x4/thread.
// ---------------------------------------------------------------------------
__global__ void gemm1_kernel(const float* __restrict__ x,
                             const float* __restrict__ W,     // W_in; Wx = rows [0,256)
                             const float* __restrict__ bias,
                             float* __restrict__ out) {
    const int BM = 64, BN = 64, BK = 16;
    __shared__ float As[BK][BM];
    __shared__ float Bs[BK][BN];

    const int tile_n = blockIdx.x;        // 0..15
    const int tile_m = blockIdx.y;        // 0..1023
    const int tid = threadIdx.x;          // 0..255
    const int tx = tid & 15;              // N direction (4 cols each)
    const int ty = tid >> 4;              // M direction (4 rows each)

    const int row0 = tile_m * BM;
    const int col0 = tile_n * BN;

    // A load: one float4 per thread: m = tid/4, k = (tid%4)*4
    const int a_m = tid >> 2;
    const int a_k = (tid & 3) << 2;
    // B load: one float4 per thread: k = tid/16, n = (tid%16)*4
    const int b_k = tid >> 4;
    const int b_n = (tid & 15) << 2;

    float acc[4][4] = {};

    for (int k0 = 0; k0 < DIMK; k0 += BK) {
        float4 av = *reinterpret_cast<const float4*>(
            &x[(size_t)(row0 + a_m) * DIMK + k0 + a_k]);
        As[a_k + 0][a_m] = av.x;
        As[a_k + 1][a_m] = av.y;
        As[a_k + 2][a_m] = av.z;
        As[a_k + 3][a_m] = av.w;
        *reinterpret_cast<float4*>(&Bs[b_k][b_n]) =
            *reinterpret_cast<const float4*>(
                &W[(size_t)(k0 + b_k) * LATENT + col0 + b_n]);
        __syncthreads();

        #pragma unroll
        for (int k = 0; k < BK; ++k) {
            float a[4], b[4];
            #pragma unroll
            for (int i = 0; i < 4; ++i) a[i] = As[k][ty * 4 + i];
            #pragma unroll
            for (int j = 0; j < 4; ++j) b[j] = Bs[k][tx * 4 + j];
            #pragma unroll
            for (int i = 0; i < 4; ++i)
                #pragma unroll
                for (int j = 0; j < 4; ++j)
                    acc[i][j] += a[i] * b[j];
        }
        __syncthreads();
    }

    // Epilogue: add bias, scatter to [T, B, L] layout.
    float4 bv = *reinterpret_cast<const float4*>(&bias[col0 + tx * 4]);
    #pragma unroll
    for (int i = 0; i < 4; ++i) {
        int r  = row0 + ty * 4 + i;
        int bi = r >> 9;          // r / T   (T = 512)
        int ti = r & (TT - 1);    // r % T
        float4 c;
        c.x = acc[i][0] + bv.x;
        c.y = acc[i][1] + bv.y;
        c.z = acc[i][2] + bv.z;
        c.w = acc[i][3] + bv.w;
        *reinterpret_cast<float4*>(
            &out[((size_t)ti * BB + bi) * LATENT + col0 + tx * 4]) = c;
    }
}

// ---------------------------------------------------------------------------
// t = 0: out[0] = tanh(out[0])      (h_prev is zero)
// ---------------------------------------------------------------------------
__global__ void tanh0_kernel(float* __restrict__ out0) {
    int i = blockIdx.x * blockDim.x + threadIdx.x;
    out0[i] = tanhf(out0[i]);
}

// ---------------------------------------------------------------------------
// Step t: out_t = tanh(out_t + hprev @ Wh)
//   M=128, N=1024, K=1024. BM=16, BN=64, BK=32 -> grid (16, 8) = 128 CTAs,
//   256 threads, 1x4 outputs/thread. Wh (4 MB) lives in L2 across steps.
// ---------------------------------------------------------------------------
__global__ void step_kernel(const float* __restrict__ hprev,  // [B, L]
                            const float* __restrict__ Wh,     // [L, L]
                            float* __restrict__ out_t) {      // [B, L] (= xw_t + b on entry)
    const int BM = 16, BN = 64, BK = 32;
    __shared__ float As[BK][BM];
    __shared__ float Bs[BK][BN];

    const int tile_n = blockIdx.x;   // 0..15
    const int tile_m = blockIdx.y;   // 0..7
    const int tid = threadIdx.x;     // 0..255
    const int tx = tid & 15;         // N direction (4 cols)
    const int ty = tid >> 4;         // M direction (1 row)

    const int row0 = tile_m * BM;
    const int col0 = tile_n * BN;

    // A tile loads: 16x32 = 512 floats, float2 per thread.
    const int a_m = tid >> 4;              // 0..15
    const int a_k = (tid & 15) << 1;       // 0,2,..,30

    float acc[4] = {0.f, 0.f, 0.f, 0.f};

    for (int k0 = 0; k0 < LATENT; k0 += BK) {
        float2 av = *reinterpret_cast<const float2*>(
            &hprev[(size_t)(row0 + a_m) * LATENT + k0 + a_k]);
        As[a_k + 0][a_m] = av.x;
        As[a_k + 1][a_m] = av.y;

        // B tile: 32x64 = 2048 floats = 512 float4, 2 per thread.
        #pragma unroll
        for (int s = 0; s < 2; ++s) {
            int j  = tid + s * 256;
            int bk = j >> 4;
            int bn = (j & 15) << 2;
            *reinterpret_cast<float4*>(&Bs[bk][bn]) =
                *reinterpret_cast<const float4*>(
                    &Wh[(size_t)(k0 + bk) * LATENT + col0 + bn]);
        }
        __syncthreads();

        #pragma unroll
        for (int k = 0; k < BK; ++k) {
            float a = As[k][ty];
            float4 bv = *reinterpret_cast<const float4*>(&Bs[k][tx * 4]);
            acc[0] += a * bv.x;
            acc[1] += a * bv.y;
            acc[2] += a * bv.z;
            acc[3] += a * bv.w;
        }
        __syncthreads();
    }

    size_t o = (size_t)(row0 + ty) * LATENT + col0 + tx * 4;
    float4 c = *reinterpret_cast<const float4*>(&out_t[o]);
    c.x = tanhf(acc[0] + c.x);
    c.y = tanhf(acc[1] + c.y);
    c.z = tanhf(acc[2] + c.z);
    c.w = tanhf(acc[3] + c.w);
    *reinterpret_cast<float4*>(&out_t[o]) = c;
}

// ---------------------------------------------------------------------------
extern "C" void kernel_launch(void* const* d_in, const int* in_sizes, int n_in,
                              void* d_out, int out_size) {
    const float* x    = (const float*)d_in[0];   // [B, T, DIM]
    const float* W    = (const float*)d_in[1];   // [DIM+LATENT, LATENT]
    const float* bias = (const float*)d_in[2];   // [LATENT]
    float* out = (float*)d_out;                  // [T, B, LATENT]

    const float* Wh = W + (size_t)DIMK * LATENT;

    // 1) xw + bias staged into out[t, b, :]
    gemm1_kernel<<<dim3(16, 1024), 256>>>(x, W, bias, out);

    // 2) t = 0: h0 = 0 -> out[0] = tanh(out[0])
    tanh0_kernel<<<(BB * LATENT) / 256, 256>>>(out);

    // 3) sequential scan, in-place on out
    for (int t = 1; t < TT; ++t) {
        step_kernel<<<dim3(16, 8), 256>>>(
            out + (size_t)(t - 1) * BB * LATENT,
            Wh,
            out + (size_t)t * BB * LATENT);
    }
}

// round 4
// speedup vs baseline: 2.2460x; 2.2460x over previous
#include <cuda_runtime.h>
#include <cuda_bf16.h>
#include <math.h>
#include <stdint.h>

#define DIMK   256
#define LATENT 1024
#define BB     128
#define TT     512
#define KSPLIT 3072          // [hi | hi | lo] x [hi ; lo ; hi]

// ---------------------------------------------------------------------------
// Scratch (__device__ globals — no allocations allowed)
// ---------------------------------------------------------------------------
__device__ __nv_bfloat16 g_B[LATENT * KSPLIT];   // B' = WhT split: [n][3072]
__device__ __nv_bfloat16 g_A[2][BB * KSPLIT];    // A' = h split, ping-pong [m][3072]

__device__ __forceinline__ uint32_t smem_u32(const void* p) {
    uint32_t a;
    asm("{ .reg .u64 t; cvta.to.shared.u64 t, %1; cvt.u32.u64 %0, t; }" : "=r"(a) : "l"(p));
    return a;
}

// ---------------------------------------------------------------------------
// prep: Wh[k][n] (fp32) -> g_B[n][0:1024]=hi, [1024:2048]=lo, [2048:3072]=hi
// ---------------------------------------------------------------------------
__global__ void prep_wh_kernel(const float* __restrict__ W) {
    const float* Wh = W + (size_t)DIMK * LATENT;
    __shared__ float tile[32][33];
    int bx = blockIdx.x * 32;   // n base
    int by = blockIdx.y * 32;   // k base
    int tx = threadIdx.x, ty = threadIdx.y;
    #pragma unroll
    for (int i = ty; i < 32; i += 8)
        tile[i][tx] = Wh[(size_t)(by + i) * LATENT + bx + tx];
    __syncthreads();
    #pragma unroll
    for (int i = ty; i < 32; i += 8) {
        float v = tile[tx][i];                        // Wh[k=by+tx][n=bx+i]
        size_t o = (size_t)(bx + i) * KSPLIT + by + tx;
        __nv_bfloat16 h = __float2bfloat16(v);
        g_B[o]        = h;
        g_B[o + 1024] = __float2bfloat16(v - __bfloat162float(h));
        g_B[o + 2048] = h;
    }
}

// ---------------------------------------------------------------------------
// GEMM1: out[t, b, :] = x[b, t, :] @ Wx + bias (fp32 SIMT)
// ---------------------------------------------------------------------------
__global__ void gemm1_kernel(const float* __restrict__ x,
                             const float* __restrict__ W,
                             const float* __restrict__ bias,
                             float* __restrict__ out) {
    const int BM = 64, BN = 64, BK = 16;
    __shared__ float As[BK][BM];
    __shared__ float Bs[BK][BN];

    const int tile_n = blockIdx.x;
    const int tile_m = blockIdx.y;
    const int tid = threadIdx.x;
    const int tx = tid & 15;
    const int ty = tid >> 4;

    const int row0 = tile_m * BM;
    const int col0 = tile_n * BN;

    const int a_m = tid >> 2;
    const int a_k = (tid & 3) << 2;
    const int b_k = tid >> 4;
    const int b_n = (tid & 15) << 2;

    float acc[4][4] = {};

    for (int k0 = 0; k0 < DIMK; k0 += BK) {
        float4 av = *reinterpret_cast<const float4*>(
            &x[(size_t)(row0 + a_m) * DIMK + k0 + a_k]);
        As[a_k + 0][a_m] = av.x;
        As[a_k + 1][a_m] = av.y;
        As[a_k + 2][a_m] = av.z;
        As[a_k + 3][a_m] = av.w;
        *reinterpret_cast<float4*>(&Bs[b_k][b_n]) =
            *reinterpret_cast<const float4*>(
                &W[(size_t)(k0 + b_k) * LATENT + col0 + b_n]);
        __syncthreads();

        #pragma unroll
        for (int k = 0; k < BK; ++k) {
            float a[4], b[4];
            #pragma unroll
            for (int i = 0; i < 4; ++i) a[i] = As[k][ty * 4 + i];
            #pragma unroll
            for (int j = 0; j < 4; ++j) b[j] = Bs[k][tx * 4 + j];
            #pragma unroll
            for (int i = 0; i < 4; ++i)
                #pragma unroll
                for (int j = 0; j < 4; ++j)
                    acc[i][j] += a[i] * b[j];
        }
        __syncthreads();
    }

    float4 bv = *reinterpret_cast<const float4*>(&bias[col0 + tx * 4]);
    #pragma unroll
    for (int i = 0; i < 4; ++i) {
        int r  = row0 + ty * 4 + i;
        int bi = r >> 9;
        int ti = r & (TT - 1);
        float4 c;
        c.x = acc[i][0] + bv.x;
        c.y = acc[i][1] + bv.y;
        c.z = acc[i][2] + bv.z;
        c.w = acc[i][3] + bv.w;
        *reinterpret_cast<float4*>(
            &out[((size_t)ti * BB + bi) * LATENT + col0 + tx * 4]) = c;
    }
}

// ---------------------------------------------------------------------------
// t = 0: out[0] = tanh(out[0]); split h0 into g_A[0]
// ---------------------------------------------------------------------------
__global__ void tanh0_kernel(float* __restrict__ out0) {
    int i = blockIdx.x * blockDim.x + threadIdx.x;
    int m = i >> 10;
    int k = i & 1023;
    float v = tanhf(out0[i]);
    out0[i] = v;
    __nv_bfloat16 h = __float2bfloat16(v);
    size_t o = (size_t)m * KSPLIT + k;
    g_A[0][o]        = h;
    g_A[0][o + 1024] = h;
    g_A[0][o + 2048] = __float2bfloat16(v - __bfloat162float(h));
}

// ---------------------------------------------------------------------------
// Step kernel: out_t = tanh(out_t + A'(h_prev) @ B'^T), bf16 mma.sync.
// M=128, N=1024, K=3072. CTA tile 64x32, grid (32, 2), 256 threads (8 warps).
// Warp tile 16x16 (wm = wid&3, wn = wid>>2): 2x m16n8k16 per k16 step.
// cp.async 2-stage pipeline, 16B XOR swizzle (conflict-free ldmatrix).
// ---------------------------------------------------------------------------
#define STEP_BM 64
#define STEP_BN 32
#define STEP_BK 128
#define NITER   (KSPLIT / STEP_BK)            // 24
#define ABUF_BYTES 16384                      // 64 rows * 256B
#define BBUF_BYTES 8192                       // 32 rows * 256B
#define STAGE_BYTES (ABUF_BYTES + BBUF_BYTES) // 24576

__device__ __forceinline__ void cp16(uint32_t dst, const void* src) {
    asm volatile("cp.async.cg.shared.global [%0], [%1], 16;" :: "r"(dst), "l"(src));
}

__global__ void __launch_bounds__(256, 1)
step_mma_kernel(float* __restrict__ out_t, int rp) {
    __shared__ __align__(128) char smem[2 * STAGE_BYTES];  // 48KB

    const int tid = threadIdx.x;
    const int lid = tid & 31;
    const int wid = tid >> 5;
    const int m0 = blockIdx.y * STEP_BM;
    const int n0 = blockIdx.x * STEP_BN;

    const uint32_t smem_base = smem_u32(smem);
    const __nv_bfloat16* gA = g_A[rp] + (size_t)m0 * KSPLIT;
    const __nv_bfloat16* gB = g_B     + (size_t)n0 * KSPLIT;

    // ---- per-thread staging coords (16B chunks) ----
    // A: 64 rows x 16 chunks = 1024 chunks -> 4/thread
    // B: 32 rows x 16 chunks = 512 chunks  -> 2/thread
    int a_r[4], a_c[4];
    #pragma unroll
    for (int j = 0; j < 4; ++j) { int ci = tid + j * 256; a_r[j] = ci >> 4; a_c[j] = ci & 15; }
    int b_r[2], b_c[2];
    #pragma unroll
    for (int j = 0; j < 2; ++j) { int ci = tid + j * 256; b_r[j] = ci >> 4; b_c[j] = ci & 15; }

    // ---- warp-tile / ldmatrix lane geometry ----
    const int wm = wid & 3;
    const int wn = wid >> 2;
    const int a_row = wm * 16 + (lid & 15);        // A smem row
    const int a_kh  = (lid >> 4) & 1;              // A k-half (0/1 -> +0/+8)
    const int b_row = wn * 16 + (((lid >> 4) & 1) << 3) + (lid & 7);
    const int b_kh  = (lid >> 3) & 1;
    const int a_swz = a_row & 15;
    const int b_swz = b_row & 15;

    float acc[8] = {};

    // ---- prologue: stage k-chunk 0 into buffer 0 ----
    {
        uint32_t sA = smem_base, sB = smem_base + ABUF_BYTES;
        #pragma unroll
        for (int j = 0; j < 4; ++j)
            cp16(sA + a_r[j] * 256 + (((a_c[j] ^ (a_r[j] & 15))) << 4),
                 gA + (size_t)a_r[j] * KSPLIT + a_c[j] * 8);
        #pragma unroll
        for (int j = 0; j < 2; ++j)
            cp16(sB + b_r[j] * 256 + (((b_c[j] ^ (b_r[j] & 15))) << 4),
                 gB + (size_t)b_r[j] * KSPLIT + b_c[j] * 8);
        asm volatile("cp.async.commit_group;");
    }

    #pragma unroll 1
    for (int i = 0; i < NITER; ++i) {
        if (i + 1 < NITER) {
            const int k0 = (i + 1) * STEP_BK;
            uint32_t sA = smem_base + ((i + 1) & 1) * STAGE_BYTES;
            uint32_t sB = sA + ABUF_BYTES;
            #pragma unroll
            for (int j = 0; j < 4; ++j)
                cp16(sA + a_r[j] * 256 + (((a_c[j] ^ (a_r[j] & 15))) << 4),
                     gA + (size_t)a_r[j] * KSPLIT + k0 + a_c[j] * 8);
            #pragma unroll
            for (int j = 0; j < 2; ++j)
                cp16(sB + b_r[j] * 256 + (((b_c[j] ^ (b_r[j] & 15))) << 4),
                     gB + (size_t)b_r[j] * KSPLIT + k0 + b_c[j] * 8);
            asm volatile("cp.async.commit_group;");
            asm volatile("cp.async.wait_group 1;");
        } else {
            asm volatile("cp.async.wait_group 0;");
        }
        __syncthreads();

        const uint32_t sA = smem_base + (i & 1) * STAGE_BYTES;
        const uint32_t sB = sA + ABUF_BYTES;
        const uint32_t aRow = sA + a_row * 256;
        const uint32_t bRow = sB + b_row * 256;

        #pragma unroll
        for (int s = 0; s < 8; ++s) {
            uint32_t aaddr = aRow + (((2 * s + a_kh) ^ a_swz) << 4);
            uint32_t baddr = bRow + (((2 * s + b_kh) ^ b_swz) << 4);
            uint32_t A0, A1, A2, A3, B0, B1, B2, B3;
            asm volatile("ldmatrix.sync.aligned.m8n8.x4.shared.b16 {%0,%1,%2,%3}, [%4];"
                         : "=r"(A0), "=r"(A1), "=r"(A2), "=r"(A3) : "r"(aaddr));
            asm volatile("ldmatrix.sync.aligned.m8n8.x4.shared.b16 {%0,%1,%2,%3}, [%4];"
                         : "=r"(B0), "=r"(B1), "=r"(B2), "=r"(B3) : "r"(baddr));
            asm volatile(
                "mma.sync.aligned.m16n8k16.row.col.f32.bf16.bf16.f32 "
                "{%0,%1,%2,%3}, {%4,%5,%6,%7}, {%8,%9}, {%0,%1,%2,%3};"
                : "+f"(acc[0]), "+f"(acc[1]), "+f"(acc[2]), "+f"(acc[3])
                : "r"(A0), "r"(A1), "r"(A2), "r"(A3), "r"(B0), "r"(B1));
            asm volatile(
                "mma.sync.aligned.m16n8k16.row.col.f32.bf16.bf16.f32 "
                "{%0,%1,%2,%3}, {%4,%5,%6,%7}, {%8,%9}, {%0,%1,%2,%3};"
                : "+f"(acc[4]), "+f"(acc[5]), "+f"(acc[6]), "+f"(acc[7])
                : "r"(A0), "r"(A1), "r"(A2), "r"(A3), "r"(B2), "r"(B3));
        }
        __syncthreads();
    }

    // ---- epilogue: tanh(acc + xw) -> out, + bf16 split into g_A[rp^1] ----
    __nv_bfloat16* aw = g_A[rp ^ 1];
    const int g = lid >> 2;        // 0..7
    const int q = lid & 3;         // 0..3

    #pragma unroll
    for (int nt = 0; nt < 2; ++nt) {
        #pragma unroll
        for (int rh = 0; rh < 2; ++rh) {
            const int row = m0 + wm * 16 + g + rh * 8;
            const int col = n0 + wn * 16 + nt * 8 + q * 2;
            const size_t oo = (size_t)row * LATENT + col;
            float2 xv = *reinterpret_cast<const float2*>(out_t + oo);
            float v0 = tanhf(xv.x + acc[nt * 4 + rh * 2 + 0]);
            float v1 = tanhf(xv.y + acc[nt * 4 + rh * 2 + 1]);
            float2 ov; ov.x = v0; ov.y = v1;
            *reinterpret_cast<float2*>(out_t + oo) = ov;

            __nv_bfloat16 h0 = __float2bfloat16(v0);
            __nv_bfloat16 h1 = __float2bfloat16(v1);
            __nv_bfloat162 hp; hp.x = h0; hp.y = h1;
            __nv_bfloat162 lp;
            lp.x = __float2bfloat16(v0 - __bfloat162float(h0));
            lp.y = __float2bfloat16(v1 - __bfloat162float(h1));

            const size_t ao = (size_t)row * KSPLIT + col;
            *reinterpret_cast<__nv_bfloat162*>(aw + ao)        = hp;
            *reinterpret_cast<__nv_bfloat162*>(aw + ao + 1024) = hp;
            *reinterpret_cast<__nv_bfloat162*>(aw + ao + 2048) = lp;
        }
    }
}

// ---------------------------------------------------------------------------
extern "C" void kernel_launch(void* const* d_in, const int* in_sizes, int n_in,
                              void* d_out, int out_size) {
    const float* x    = (const float*)d_in[0];   // [B, T, DIM]
    const float* W    = (const float*)d_in[1];   // [DIM+LATENT, LATENT]
    const float* bias = (const float*)d_in[2];   // [LATENT]
    float* out = (float*)d_out;                  // [T, B, LATENT]

    // 0) Wh transpose + bf16 hi/lo split -> g_B
    prep_wh_kernel<<<dim3(32, 32), dim3(32, 8)>>>(W);

    // 1) xw + bias staged into out[t, b, :]
    gemm1_kernel<<<dim3(16, 1024), 256>>>(x, W, bias, out);

    // 2) t = 0
    tanh0_kernel<<<(BB * LATENT) / 256, 256>>>(out);

    // 3) sequential scan on tensor cores (mma.sync bf16, split-K correction)
    for (int t = 1; t < TT; ++t) {
        step_mma_kernel<<<dim3(32, 2), 256>>>(
            out + (size_t)t * BB * LATENT, (t - 1) & 1);
    }
}

// round 5
// speedup vs baseline: 3.3850x; 1.5072x over previous
#include <cuda_runtime.h>
#include <cuda_bf16.h>
#include <math.h>
#include <stdint.h>

#define DIMK   256
#define LATENT 1024
#define BB     128
#define TT     512
#define KSPLIT 3072          // B' columns: [hi | lo | hi]
#define KA     2048          // A' columns: [hi | lo] (hi re-read for chunks 8-15)
#define NCHUNK 24
#define NCTA   128

// ---------------------------------------------------------------------------
// Scratch (__device__ globals — no allocations allowed)
// ---------------------------------------------------------------------------
__device__ __nv_bfloat16 g_B[LATENT * KSPLIT];   // B' = WhT split: [n][3072]
__device__ __nv_bfloat16 g_A2[2][BB * KA];       // A' = h split [m][2048], ping-pong
__device__ unsigned g_bar_count;
__device__ volatile unsigned g_bar_epoch;

__device__ __forceinline__ uint32_t smem_u32(const void* p) {
    uint32_t a;
    asm("{ .reg .u64 t; cvta.to.shared.u64 t, %1; cvt.u32.u64 %0, t; }" : "=r"(a) : "l"(p));
    return a;
}
__device__ __forceinline__ void cp16(uint32_t dst, const void* src) {
    asm volatile("cp.async.cg.shared.global [%0], [%1], 16;" :: "r"(dst), "l"(src));
}

// ---------------------------------------------------------------------------
// prep: Wh[k][n] (fp32) -> g_B[n][0:1024]=hi, [1024:2048]=lo, [2048:3072]=hi
// ---------------------------------------------------------------------------
__global__ void prep_wh_kernel(const float* __restrict__ W) {
    const float* Wh = W + (size_t)DIMK * LATENT;
    __shared__ float tile[32][33];
    int bx = blockIdx.x * 32;   // n base
    int by = blockIdx.y * 32;   // k base
    int tx = threadIdx.x, ty = threadIdx.y;
    #pragma unroll
    for (int i = ty; i < 32; i += 8)
        tile[i][tx] = Wh[(size_t)(by + i) * LATENT + bx + tx];
    __syncthreads();
    #pragma unroll
    for (int i = ty; i < 32; i += 8) {
        float v = tile[tx][i];                        // Wh[k=by+tx][n=bx+i]
        size_t o = (size_t)(bx + i) * KSPLIT + by + tx;
        __nv_bfloat16 h = __float2bfloat16(v);
        g_B[o]        = h;
        g_B[o + 1024] = __float2bfloat16(v - __bfloat162float(h));
        g_B[o + 2048] = h;
    }
}

// ---------------------------------------------------------------------------
// GEMM1: out[t, b, :] = x[b, t, :] @ Wx + bias (fp32 SIMT)
// ---------------------------------------------------------------------------
__global__ void gemm1_kernel(const float* __restrict__ x,
                             const float* __restrict__ W,
                             const float* __restrict__ bias,
                             float* __restrict__ out) {
    const int BM = 64, BN = 64, BK = 16;
    __shared__ float As[BK][BM];
    __shared__ float Bs[BK][BN];

    const int tile_n = blockIdx.x;
    const int tile_m = blockIdx.y;
    const int tid = threadIdx.x;
    const int tx = tid & 15;
    const int ty = tid >> 4;

    const int row0 = tile_m * BM;
    const int col0 = tile_n * BN;

    const int a_m = tid >> 2;
    const int a_k = (tid & 3) << 2;
    const int b_k = tid >> 4;
    const int b_n = (tid & 15) << 2;

    float acc[4][4] = {};

    for (int k0 = 0; k0 < DIMK; k0 += BK) {
        float4 av = *reinterpret_cast<const float4*>(
            &x[(size_t)(row0 + a_m) * DIMK + k0 + a_k]);
        As[a_k + 0][a_m] = av.x;
        As[a_k + 1][a_m] = av.y;
        As[a_k + 2][a_m] = av.z;
        As[a_k + 3][a_m] = av.w;
        *reinterpret_cast<float4*>(&Bs[b_k][b_n]) =
            *reinterpret_cast<const float4*>(
                &W[(size_t)(k0 + b_k) * LATENT + col0 + b_n]);
        __syncthreads();

        #pragma unroll
        for (int k = 0; k < BK; ++k) {
            float a[4], b[4];
            #pragma unroll
            for (int i = 0; i < 4; ++i) a[i] = As[k][ty * 4 + i];
            #pragma unroll
            for (int j = 0; j < 4; ++j) b[j] = Bs[k][tx * 4 + j];
            #pragma unroll
            for (int i = 0; i < 4; ++i)
                #pragma unroll
                for (int j = 0; j < 4; ++j)
                    acc[i][j] += a[i] * b[j];
        }
        __syncthreads();
    }

    float4 bv = *reinterpret_cast<const float4*>(&bias[col0 + tx * 4]);
    #pragma unroll
    for (int i = 0; i < 4; ++i) {
        int r  = row0 + ty * 4 + i;
        int bi = r >> 9;
        int ti = r & (TT - 1);
        float4 c;
        c.x = acc[i][0] + bv.x;
        c.y = acc[i][1] + bv.y;
        c.z = acc[i][2] + bv.z;
        c.w = acc[i][3] + bv.w;
        *reinterpret_cast<float4*>(
            &out[((size_t)ti * BB + bi) * LATENT + col0 + tx * 4]) = c;
    }
}

// ---------------------------------------------------------------------------
// t = 0: out[0] = tanh(out[0]); split h0 into g_A2[0]; reset barrier state
// ---------------------------------------------------------------------------
__global__ void tanh0_kernel(float* __restrict__ out0) {
    int i = blockIdx.x * blockDim.x + threadIdx.x;
    if (i == 0) { g_bar_count = 0; g_bar_epoch = 0; }
    int m = i >> 10;
    int k = i & 1023;
    float v = tanhf(out0[i]);
    out0[i] = v;
    __nv_bfloat16 h = __float2bfloat16(v);
    size_t o = (size_t)m * KA + k;
    g_A2[0][o]        = h;
    g_A2[0][o + 1024] = __float2bfloat16(v - __bfloat162float(h));
}

// ---------------------------------------------------------------------------
// Persistent scan kernel: 128 CTAs (4 m-tiles x 32 n-tiles of 32x32), 128 thr.
// B' slice (32 x 3072 bf16, 192KB) resident in smem for all 511 steps.
// Per step: stream A' (hi|lo dedup) via 3-stage cp.async, 24 x 8 k16 MMAs,
// fused tanh epilogue + bf16 hi/lo split, software grid barrier.
// ---------------------------------------------------------------------------
#define SMB_BYTES (NCHUNK * 8192)                 // 196608
#define SMA_OFF   SMB_BYTES
#define SMEM_SCAN (SMB_BYTES + 3 * 8192)          // 221184

__global__ void __launch_bounds__(128, 1)
scan_kernel(float* __restrict__ out) {
    extern __shared__ char smem[];
    const int tid = threadIdx.x;
    const int lid = tid & 31;
    const int wid = tid >> 5;
    const int bid = blockIdx.x;
    const int m0 = (bid & 3) * 32;
    const int n0 = (bid >> 2) * 32;

    const uint32_t smB = smem_u32(smem);
    const uint32_t smA = smB + SMA_OFF;

    // ---- load resident B' slice: 24 chunks of [32 rows x 128 cols] bf16 ----
    {
        const __nv_bfloat16* gB = g_B + (size_t)n0 * KSPLIT;
        #pragma unroll 1
        for (int j = 0; j < 96; ++j) {
            int ci = tid + j * 128;
            int ch = ci >> 9;
            int rw = (ci >> 4) & 31;
            int cc = ci & 15;
            cp16(smB + ch * 8192 + rw * 256 + (((cc ^ (rw & 15))) << 4),
                 gB + (size_t)rw * KSPLIT + ch * 128 + cc * 8);
        }
        asm volatile("cp.async.commit_group;");
        asm volatile("cp.async.wait_group 0;");
        __syncthreads();
    }

    // ---- lane geometry (verified in round 4) ----
    const int wm = wid & 1;             // 2 m-warps of 16
    const int wn = wid >> 1;            // 2 n-warps of 16
    const int a_row = wm * 16 + (lid & 15);
    const int a_kh  = (lid >> 4) & 1;
    const int b_row = wn * 16 + (((lid >> 4) & 1) << 3) + (lid & 7);
    const int b_kh  = (lid >> 3) & 1;
    const int a_swz = a_row & 15;
    const int b_swz = b_row & 15;
    const int g = lid >> 2;
    const int q = lid & 3;

    // A staging coords: 4 x 16B per thread per chunk
    int s_rw[4], s_cc[4];
    #pragma unroll
    for (int j = 0; j < 4; ++j) {
        int ci = tid + j * 128;
        s_rw[j] = ci >> 4;
        s_cc[j] = ci & 15;
    }

    for (int t = 1; t < TT; ++t) {
        const int rp = (t - 1) & 1;
        const __nv_bfloat16* gA = g_A2[rp] + (size_t)m0 * KA;
        __nv_bfloat16* aw = g_A2[rp ^ 1];
        float* out_t = out + (size_t)t * BB * LATENT;

        // ---- prologue: chunks 0,1 into bufs 0,1 (A column map: hi|hi|lo) ----
        #pragma unroll
        for (int p = 0; p < 2; ++p) {
            const int ab = p * 128;   // chunks 0,1 are in hi region
            uint32_t dst = smA + p * 8192;
            #pragma unroll
            for (int j = 0; j < 4; ++j)
                cp16(dst + s_rw[j] * 256 + (((s_cc[j] ^ (s_rw[j] & 15))) << 4),
                     gA + (size_t)s_rw[j] * KA + ab + s_cc[j] * 8);
            asm volatile("cp.async.commit_group;");
        }

        // ---- prefetch xw for this tile (hides DRAM latency under MMA) ----
        float2 xv[4];
        #pragma unroll
        for (int nt = 0; nt < 2; ++nt)
            #pragma unroll
            for (int rh = 0; rh < 2; ++rh) {
                int row = m0 + wm * 16 + g + rh * 8;
                int col = n0 + wn * 16 + nt * 8 + q * 2;
                xv[nt * 2 + rh] = *reinterpret_cast<const float2*>(
                    out_t + (size_t)row * LATENT + col);
            }

        float acc[8] = {};
        int buf = 0;        // buffer holding chunk i
        int nbuf = 2;       // buffer to fill with chunk i+2

        #pragma unroll 1
        for (int i = 0; i < NCHUNK; ++i) {
            // stage chunk i+2 (may be an empty commit group at the tail)
            if (i + 2 < NCHUNK) {
                const int c = i + 2;
                const int ab = (c < 8) ? c * 128
                             : (c < 16) ? (c - 8) * 128
                                        : 1024 + (c - 16) * 128;
                uint32_t dst = smA + nbuf * 8192;
                #pragma unroll
                for (int j = 0; j < 4; ++j)
                    cp16(dst + s_rw[j] * 256 + (((s_cc[j] ^ (s_rw[j] & 15))) << 4),
                         gA + (size_t)s_rw[j] * KA + ab + s_cc[j] * 8);
            }
            asm volatile("cp.async.commit_group;");
            asm volatile("cp.async.wait_group 2;");
            __syncthreads();

            const uint32_t aR = smA + buf * 8192 + a_row * 256;
            const uint32_t bR = smB + i * 8192 + b_row * 256;

            #pragma unroll
            for (int s = 0; s < 8; ++s) {
                uint32_t aaddr = aR + (((2 * s + a_kh) ^ a_swz) << 4);
                uint32_t baddr = bR + (((2 * s + b_kh) ^ b_swz) << 4);
                uint32_t A0, A1, A2, A3, B0, B1, B2, B3;
                asm volatile("ldmatrix.sync.aligned.m8n8.x4.shared.b16 {%0,%1,%2,%3}, [%4];"
                             : "=r"(A0), "=r"(A1), "=r"(A2), "=r"(A3) : "r"(aaddr));
                asm volatile("ldmatrix.sync.aligned.m8n8.x4.shared.b16 {%0,%1,%2,%3}, [%4];"
                             : "=r"(B0), "=r"(B1), "=r"(B2), "=r"(B3) : "r"(baddr));
                asm volatile(
                    "mma.sync.aligned.m16n8k16.row.col.f32.bf16.bf16.f32 "
                    "{%0,%1,%2,%3}, {%4,%5,%6,%7}, {%8,%9}, {%0,%1,%2,%3};"
                    : "+f"(acc[0]), "+f"(acc[1]), "+f"(acc[2]), "+f"(acc[3])
                    : "r"(A0), "r"(A1), "r"(A2), "r"(A3), "r"(B0), "r"(B1));
                asm volatile(
                    "mma.sync.aligned.m16n8k16.row.col.f32.bf16.bf16.f32 "
                    "{%0,%1,%2,%3}, {%4,%5,%6,%7}, {%8,%9}, {%0,%1,%2,%3};"
                    : "+f"(acc[4]), "+f"(acc[5]), "+f"(acc[6]), "+f"(acc[7])
                    : "r"(A0), "r"(A1), "r"(A2), "r"(A3), "r"(B2), "r"(B3));
            }
            buf = (buf == 2) ? 0 : buf + 1;
            nbuf = (nbuf == 2) ? 0 : nbuf + 1;
        }

        // ---- epilogue: tanh(acc + xw) -> out; bf16 hi/lo split -> g_A2[wp] ----
        #pragma unroll
        for (int nt = 0; nt < 2; ++nt) {
            #pragma unroll
            for (int rh = 0; rh < 2; ++rh) {
                const int row = m0 + wm * 16 + g + rh * 8;
                const int col = n0 + wn * 16 + nt * 8 + q * 2;
                float2 x2 = xv[nt * 2 + rh];
                float v0 = tanhf(x2.x + acc[nt * 4 + rh * 2 + 0]);
                float v1 = tanhf(x2.y + acc[nt * 4 + rh * 2 + 1]);
                float2 ov; ov.x = v0; ov.y = v1;
                *reinterpret_cast<float2*>(out_t + (size_t)row * LATENT + col) = ov;

                __nv_bfloat16 h0 = __float2bfloat16(v0);
                __nv_bfloat16 h1 = __float2bfloat16(v1);
                __nv_bfloat162 hp; hp.x = h0; hp.y = h1;
                __nv_bfloat162 lp;
                lp.x = __float2bfloat16(v0 - __bfloat162float(h0));
                lp.y = __float2bfloat16(v1 - __bfloat162float(h1));
                const size_t ao = (size_t)row * KA + col;
                *reinterpret_cast<__nv_bfloat162*>(aw + ao)        = hp;
                *reinterpret_cast<__nv_bfloat162*>(aw + ao + 1024) = lp;
            }
        }

        // ---- software grid barrier (monotonic epoch) ----
        if (t + 1 < TT) {
            __threadfence();
            __syncthreads();
            if (tid == 0) {
                unsigned old = atomicAdd(&g_bar_count, 1u);
                if (old == (unsigned)(t * NCTA - 1)) {
                    g_bar_epoch = (unsigned)t;          // release
                } else {
                    while (g_bar_epoch < (unsigned)t) { }
                    __threadfence();
                }
            }
            __syncthreads();
        }
    }
}

// ---------------------------------------------------------------------------
extern "C" void kernel_launch(void* const* d_in, const int* in_sizes, int n_in,
                              void* d_out, int out_size) {
    const float* x    = (const float*)d_in[0];   // [B, T, DIM]
    const float* W    = (const float*)d_in[1];   // [DIM+LATENT, LATENT]
    const float* bias = (const float*)d_in[2];   // [LATENT]
    float* out = (float*)d_out;                  // [T, B, LATENT]

    static int configured = 0;
    if (!configured) {
        cudaFuncSetAttribute(scan_kernel,
                             cudaFuncAttributeMaxDynamicSharedMemorySize,
                             SMEM_SCAN);
        configured = 1;
    }

    // 0) Wh transpose + bf16 hi/lo split -> g_B
    prep_wh_kernel<<<dim3(32, 32), dim3(32, 8)>>>(W);

    // 1) xw + bias staged into out[t, b, :]
    gemm1_kernel<<<dim3(16, 1024), 256>>>(x, W, bias, out);

    // 2) t = 0 (+ barrier state reset)
    tanh0_kernel<<<(BB * LATENT) / 256, 256>>>(out);

    // 3) persistent tensor-core scan for t = 1..511
    scan_kernel<<<NCTA, 128, SMEM_SCAN>>>(out);
}

// round 6
// speedup vs baseline: 4.3690x; 1.2907x over previous
#include <cuda_runtime.h>
#include <cuda_bf16.h>
#include <math.h>
#include <stdint.h>

#define DIMK   256
#define LATENT 1024
#define BB     128
#define TT     512
#define KSPLIT 3072          // B' (scan) columns: [hi | lo | hi]
#define KA     2048          // A' (scan) columns: [hi | lo]
#define NCHUNK 24
#define NCTA   128

// ---------------------------------------------------------------------------
// Scratch (__device__ globals — no allocations allowed)
// ---------------------------------------------------------------------------
__device__ __nv_bfloat16 g_B[LATENT * KSPLIT];          // scan B' = WhT split [n][3072]
__device__ __nv_bfloat16 g_A2[2][BB * KA];              // scan A' ping-pong [m][2048]
__device__ __nv_bfloat16 g_X[(size_t)BB * TT * 512];    // gemm1 A' = x split [r][hi256|lo256]
__device__ __nv_bfloat16 g_BX[LATENT * 512];            // gemm1 B' = WxT split [n][hi256|lo256]
__device__ unsigned g_bar_count;
__device__ volatile unsigned g_bar_epoch;

__device__ __forceinline__ uint32_t smem_u32(const void* p) {
    uint32_t a;
    asm("{ .reg .u64 t; cvta.to.shared.u64 t, %1; cvt.u32.u64 %0, t; }" : "=r"(a) : "l"(p));
    return a;
}
__device__ __forceinline__ void cp16(uint32_t dst, const void* src) {
    asm volatile("cp.async.cg.shared.global [%0], [%1], 16;" :: "r"(dst), "l"(src));
}
#define CP_COMMIT() asm volatile("cp.async.commit_group;")
#define CP_WAIT(n)  asm volatile("cp.async.wait_group %0;" :: "n"(n))
#define BARQ(id)    asm volatile("bar.sync %0, 128;" :: "r"(id) : "memory")

#define LDSM4(r0, r1, r2, r3, addr) \
    asm volatile("ldmatrix.sync.aligned.m8n8.x4.shared.b16 {%0,%1,%2,%3}, [%4];" \
                 : "=r"(r0), "=r"(r1), "=r"(r2), "=r"(r3) : "r"(addr))
#define MMA16816(d, a0, a1, a2, a3, b0, b1) \
    asm volatile("mma.sync.aligned.m16n8k16.row.col.f32.bf16.bf16.f32 " \
                 "{%0,%1,%2,%3}, {%4,%5,%6,%7}, {%8,%9}, {%0,%1,%2,%3};" \
                 : "+f"((d)[0]), "+f"((d)[1]), "+f"((d)[2]), "+f"((d)[3]) \
                 : "r"(a0), "r"(a1), "r"(a2), "r"(a3), "r"(b0), "r"(b1))

// ---------------------------------------------------------------------------
// prep: Wh[k][n] -> g_B[n][0:1024]=hi, [1024:2048]=lo, [2048:3072]=hi
// ---------------------------------------------------------------------------
__global__ void prep_wh_kernel(const float* __restrict__ W) {
    const float* Wh = W + (size_t)DIMK * LATENT;
    __shared__ float tile[32][33];
    int bx = blockIdx.x * 32;   // n base
    int by = blockIdx.y * 32;   // k base
    int tx = threadIdx.x, ty = threadIdx.y;
    #pragma unroll
    for (int i = ty; i < 32; i += 8)
        tile[i][tx] = Wh[(size_t)(by + i) * LATENT + bx + tx];
    __syncthreads();
    #pragma unroll
    for (int i = ty; i < 32; i += 8) {
        float v = tile[tx][i];
        size_t o = (size_t)(bx + i) * KSPLIT + by + tx;
        __nv_bfloat16 h = __float2bfloat16(v);
        g_B[o]        = h;
        g_B[o + 1024] = __float2bfloat16(v - __bfloat162float(h));
        g_B[o + 2048] = h;
    }
}

// ---------------------------------------------------------------------------
// prep: Wx[k][n] (k<256) -> g_BX[n][k]=hi, [n][256+k]=lo
// ---------------------------------------------------------------------------
__global__ void prep_bx_kernel(const float* __restrict__ W) {
    __shared__ float tile[32][33];
    int bx = blockIdx.x * 32;   // n base
    int by = blockIdx.y * 32;   // k base (0..224)
    int tx = threadIdx.x, ty = threadIdx.y;
    #pragma unroll
    for (int i = ty; i < 32; i += 8)
        tile[i][tx] = W[(size_t)(by + i) * LATENT + bx + tx];
    __syncthreads();
    #pragma unroll
    for (int i = ty; i < 32; i += 8) {
        float v = tile[tx][i];                       // Wx[k=by+tx][n=bx+i]
        size_t o = (size_t)(bx + i) * 512 + by + tx;
        __nv_bfloat16 h = __float2bfloat16(v);
        g_BX[o]       = h;
        g_BX[o + 256] = __float2bfloat16(v - __bfloat162float(h));
    }
}

// ---------------------------------------------------------------------------
// prep: x[r][d] fp32 -> g_X[r][d]=hi, g_X[r][256+d]=lo  (r = b*T + t)
// ---------------------------------------------------------------------------
__global__ void prep_x_kernel(const float* __restrict__ x) {
    size_t idx = (size_t)blockIdx.x * 256 + threadIdx.x;
    size_t e = idx * 4;
    size_t r = e >> 8;
    int d = (int)(e & 255);
    float4 v = *reinterpret_cast<const float4*>(x + e);
    __nv_bfloat16 h0 = __float2bfloat16(v.x), h1 = __float2bfloat16(v.y);
    __nv_bfloat16 h2 = __float2bfloat16(v.z), h3 = __float2bfloat16(v.w);
    __nv_bfloat162 hp0; hp0.x = h0; hp0.y = h1;
    __nv_bfloat162 hp1; hp1.x = h2; hp1.y = h3;
    __nv_bfloat162 lp0, lp1;
    lp0.x = __float2bfloat16(v.x - __bfloat162float(h0));
    lp0.y = __float2bfloat16(v.y - __bfloat162float(h1));
    lp1.x = __float2bfloat16(v.z - __bfloat162float(h2));
    lp1.y = __float2bfloat16(v.w - __bfloat162float(h3));
    size_t o = r * 512 + d;
    *reinterpret_cast<__nv_bfloat162*>(&g_X[o + 0])   = hp0;
    *reinterpret_cast<__nv_bfloat162*>(&g_X[o + 2])   = hp1;
    *reinterpret_cast<__nv_bfloat162*>(&g_X[o + 256]) = lp0;
    *reinterpret_cast<__nv_bfloat162*>(&g_X[o + 258]) = lp1;
}

// ---------------------------------------------------------------------------
// GEMM1 (tensor): out[t,b,:] = x @ Wx + b.  M=65536, N=1024, K'=768 (6 chunks,
// A dedup [hi|lo] 512). CTA: 64 rows, loops all 16 n-tiles of 64. A resident
// in smem (64KB), B double-buffered (2x16KB). 8 warps, 2 CTAs/SM.
// ---------------------------------------------------------------------------
#define G1_SMA   0
#define G1_SMB   65536
#define G1_SMEM  (65536 + 2 * 16384)

__global__ void __launch_bounds__(256, 2)
gemm1_mma_kernel(const float* __restrict__ bias, float* __restrict__ out) {
    extern __shared__ char smem[];
    const uint32_t smA = smem_u32(smem);
    const uint32_t smB = smA + G1_SMB;
    const int tid = threadIdx.x;
    const int lid = tid & 31;
    const int wid = tid >> 5;
    const int r0 = blockIdx.x * 64;

    // ---- load resident A' tile: 64 rows x 512 cols bf16 (4 chunks) ----
    {
        const __nv_bfloat16* gA = g_X + (size_t)r0 * 512;
        #pragma unroll
        for (int j = 0; j < 16; ++j) {
            int ci = tid + j * 256;
            int ch = ci >> 10;
            int rem = ci & 1023;
            int rw = rem >> 4;
            int cc = rem & 15;
            cp16(smA + ch * 16384 + rw * 256 + (((cc ^ (rw & 15))) << 4),
                 gA + (size_t)rw * 512 + ch * 128 + cc * 8);
        }
        CP_COMMIT();
    }

    // ---- stage B chunk g=0 ----
    {
        #pragma unroll
        for (int j = 0; j < 4; ++j) {
            int ci = tid + j * 256;
            int rw = ci >> 4;
            int cc = ci & 15;
            cp16(smB + rw * 256 + (((cc ^ (rw & 15))) << 4),
                 g_BX + (size_t)rw * 512 + cc * 8);
        }
        CP_COMMIT();
    }

    // ---- lane geometry ----
    const int wm = wid & 1;
    const int wn = wid >> 1;
    const int a_row0 = wm * 32 + (lid & 15);
    const int a_row1 = a_row0 + 16;
    const int a_kh   = (lid >> 4) & 1;
    const int b_row  = wn * 16 + (((lid >> 4) & 1) << 3) + (lid & 7);
    const int b_kh   = (lid >> 3) & 1;
    const int a_swz0 = a_row0 & 15, a_swz1 = a_row1 & 15, b_swz = b_row & 15;
    const int g8 = lid >> 2;
    const int q  = lid & 3;

    float acc[4][4];

    #pragma unroll 1
    for (int gg = 0; gg < 96; ++gg) {
        const int nt = gg / 6;
        const int c  = gg % 6;

        if (gg + 1 < 96) {
            const int nt2 = (gg + 1) / 6;
            const int c2  = (gg + 1) % 6;
            const int cb  = (c2 & 3) * 128;        // B col map: hi,hi2,lo,lo2,hi,hi2
            uint32_t dst = smB + ((gg + 1) & 1) * 16384;
            const __nv_bfloat16* gBn = g_BX + (size_t)(nt2 * 64) * 512;
            #pragma unroll
            for (int j = 0; j < 4; ++j) {
                int ci = tid + j * 256;
                int rw = ci >> 4;
                int cc = ci & 15;
                cp16(dst + rw * 256 + (((cc ^ (rw & 15))) << 4),
                     gBn + (size_t)rw * 512 + cb + cc * 8);
            }
            CP_COMMIT();
            CP_WAIT(1);
        } else {
            CP_WAIT(0);
        }
        __syncthreads();

        if (c == 0) {
            #pragma unroll
            for (int i = 0; i < 4; ++i)
                #pragma unroll
                for (int j = 0; j < 4; ++j) acc[i][j] = 0.f;
        }

        const int ach = (c < 2) ? c : c - 2;       // A chunk: 0,1,0,1,2,3
        const uint32_t aR0 = smA + ach * 16384 + a_row0 * 256;
        const uint32_t aR1 = smA + ach * 16384 + a_row1 * 256;
        const uint32_t bR  = smB + (gg & 1) * 16384 + b_row * 256;

        #pragma unroll
        for (int s = 0; s < 8; ++s) {
            uint32_t A0, A1, A2, A3, C0, C1, C2, C3, B0, B1, B2, B3;
            LDSM4(A0, A1, A2, A3, aR0 + (((2 * s + a_kh) ^ a_swz0) << 4));
            LDSM4(C0, C1, C2, C3, aR1 + (((2 * s + a_kh) ^ a_swz1) << 4));
            LDSM4(B0, B1, B2, B3, bR  + (((2 * s + b_kh) ^ b_swz) << 4));
            MMA16816(acc[0], A0, A1, A2, A3, B0, B1);
            MMA16816(acc[1], A0, A1, A2, A3, B2, B3);
            MMA16816(acc[2], C0, C1, C2, C3, B0, B1);
            MMA16816(acc[3], C0, C1, C2, C3, B2, B3);
        }

        if (c == 5) {
            const int n0 = nt * 64;
            #pragma unroll
            for (int f = 0; f < 2; ++f) {
                #pragma unroll
                for (int ntf = 0; ntf < 2; ++ntf) {
                    const int col = n0 + wn * 16 + ntf * 8 + q * 2;
                    float2 bv = *reinterpret_cast<const float2*>(bias + col);
                    #pragma unroll
                    for (int rh = 0; rh < 2; ++rh) {
                        const int r = r0 + wm * 32 + f * 16 + g8 + rh * 8;
                        const int bi = r >> 9;
                        const int ti = r & (TT - 1);
                        float2 o;
                        o.x = acc[f * 2 + ntf][rh * 2 + 0] + bv.x;
                        o.y = acc[f * 2 + ntf][rh * 2 + 1] + bv.y;
                        *reinterpret_cast<float2*>(
                            &out[((size_t)ti * BB + bi) * LATENT + col]) = o;
                    }
                }
            }
        }
        __syncthreads();
    }
}

// ---------------------------------------------------------------------------
// t = 0: out[0] = tanh(out[0]); split h0 into g_A2[0]; reset barrier state
// ---------------------------------------------------------------------------
__global__ void tanh0_kernel(float* __restrict__ out0) {
    int i = blockIdx.x * blockDim.x + threadIdx.x;
    if (i == 0) { g_bar_count = 0; g_bar_epoch = 0; }
    int m = i >> 10;
    int k = i & 1023;
    float v = tanhf(out0[i]);
    out0[i] = v;
    __nv_bfloat16 h = __float2bfloat16(v);
    size_t o = (size_t)m * KA + k;
    g_A2[0][o]        = h;
    g_A2[0][o + 1024] = __float2bfloat16(v - __bfloat162float(h));
}

// ---------------------------------------------------------------------------
// Persistent scan: 128 CTAs (4m x 32n tiles of 32x32), 256 threads = 2 quads.
// Split-K: quad0 chunks 0-11, quad1 chunks 12-23, smem reduction, quad0 epi.
// B' slice (192KB) resident; per-quad A double-buffer (2x8KB each).
// ---------------------------------------------------------------------------
#define SMB_BYTES (NCHUNK * 8192)                 // 196608
#define SMEM_SCAN (SMB_BYTES + 4 * 8192)          // 229376

__global__ void __launch_bounds__(256, 1)
scan_kernel(float* __restrict__ out) {
    extern __shared__ char smem[];
    const int tid = threadIdx.x;
    const int lid = tid & 31;
    const int wid = tid >> 5;
    const int Q = wid >> 2;             // quad id
    const int qwid = wid & 3;
    const int qtid = tid & 127;
    const int bid = blockIdx.x;
    const int m0 = (bid & 3) * 32;
    const int n0 = (bid >> 2) * 32;

    const uint32_t smB = smem_u32(smem);
    const uint32_t smA = smB + SMB_BYTES;           // 4 x 8KB: quad0 bufs 0,1; quad1 bufs 2,3
    const uint32_t qbuf = smA + Q * 16384;

    // ---- load resident B' slice: 24 chunks of [32 x 128] bf16 ----
    {
        const __nv_bfloat16* gB = g_B + (size_t)n0 * KSPLIT;
        #pragma unroll 1
        for (int j = 0; j < 48; ++j) {
            int ci = tid + j * 256;
            int ch = ci >> 9;
            int rw = (ci >> 4) & 31;
            int cc = ci & 15;
            cp16(smB + ch * 8192 + rw * 256 + (((cc ^ (rw & 15))) << 4),
                 gB + (size_t)rw * KSPLIT + ch * 128 + cc * 8);
        }
        CP_COMMIT();
        CP_WAIT(0);
        __syncthreads();
    }

    // ---- lane geometry ----
    const int wm = qwid & 1;
    const int wn = qwid >> 1;
    const int a_row = wm * 16 + (lid & 15);
    const int a_kh  = (lid >> 4) & 1;
    const int b_row = wn * 16 + (((lid >> 4) & 1) << 3) + (lid & 7);
    const int b_kh  = (lid >> 3) & 1;
    const int a_swz = a_row & 15;
    const int b_swz = b_row & 15;
    const int g = lid >> 2;
    const int q = lid & 3;
    const int cstart = Q * 12;

    // A staging coords: 4 x 16B per thread per chunk (128 threads per quad)
    int s_rw[4], s_cc[4];
    #pragma unroll
    for (int j = 0; j < 4; ++j) {
        int ci = qtid + j * 128;
        s_rw[j] = ci >> 4;
        s_cc[j] = ci & 15;
    }

    for (int t = 1; t < TT; ++t) {
        const int rp = (t - 1) & 1;
        const __nv_bfloat16* gA = g_A2[rp] + (size_t)m0 * KA;
        __nv_bfloat16* aw = g_A2[rp ^ 1];
        float* out_t = out + (size_t)t * BB * LATENT;

        // ---- prologue: stage this quad's chunk 0 ----
        {
            const int c = cstart;
            const int ab = (c < 8) ? c * 128 : (c < 16) ? (c - 8) * 128
                                                        : 1024 + (c - 16) * 128;
            #pragma unroll
            for (int j = 0; j < 4; ++j)
                cp16(qbuf + s_rw[j] * 256 + (((s_cc[j] ^ (s_rw[j] & 15))) << 4),
                     gA + (size_t)s_rw[j] * KA + ab + s_cc[j] * 8);
            CP_COMMIT();
        }

        // ---- xw prefetch (quad0 only; hides DRAM under MMA) ----
        float2 xv[4];
        if (Q == 0) {
            #pragma unroll
            for (int nt = 0; nt < 2; ++nt)
                #pragma unroll
                for (int rh = 0; rh < 2; ++rh) {
                    int row = m0 + wm * 16 + g + rh * 8;
                    int col = n0 + wn * 16 + nt * 8 + q * 2;
                    xv[nt * 2 + rh] = *reinterpret_cast<const float2*>(
                        out_t + (size_t)row * LATENT + col);
                }
        }

        float acc[8] = {};

        #pragma unroll 1
        for (int i = 0; i < 12; ++i) {
            if (i + 1 < 12) {
                const int c = cstart + i + 1;
                const int ab = (c < 8) ? c * 128 : (c < 16) ? (c - 8) * 128
                                                            : 1024 + (c - 16) * 128;
                uint32_t dst = qbuf + ((i + 1) & 1) * 8192;
                #pragma unroll
                for (int j = 0; j < 4; ++j)
                    cp16(dst + s_rw[j] * 256 + (((s_cc[j] ^ (s_rw[j] & 15))) << 4),
                         gA + (size_t)s_rw[j] * KA + ab + s_cc[j] * 8);
                CP_COMMIT();
                CP_WAIT(1);
            } else {
                CP_WAIT(0);
            }
            BARQ(Q + 1);                                 // staged data visible

            const uint32_t aR = qbuf + (i & 1) * 8192 + a_row * 256;
            const uint32_t bR = smB + (cstart + i) * 8192 + b_row * 256;

            #pragma unroll
            for (int s = 0; s < 8; ++s) {
                uint32_t A0, A1, A2, A3, B0, B1, B2, B3;
                LDSM4(A0, A1, A2, A3, aR + (((2 * s + a_kh) ^ a_swz) << 4));
                LDSM4(B0, B1, B2, B3, bR + (((2 * s + b_kh) ^ b_swz) << 4));
                MMA16816(acc,     A0, A1, A2, A3, B0, B1);
                MMA16816(acc + 4, A0, A1, A2, A3, B2, B3);
            }
            BARQ(Q + 1);                                 // consume done, next stage safe
        }

        // ---- reduction: quad1 partials -> smem, quad0 adds + epilogue ----
        __syncthreads();
        if (Q == 1) {
            #pragma unroll
            for (int nt = 0; nt < 2; ++nt)
                #pragma unroll
                for (int rh = 0; rh < 2; ++rh) {
                    int r_l = wm * 16 + g + rh * 8;
                    int c_l = wn * 16 + nt * 8 + q * 2;
                    float2 pv;
                    pv.x = acc[nt * 4 + rh * 2 + 0];
                    pv.y = acc[nt * 4 + rh * 2 + 1];
                    *reinterpret_cast<float2*>(smem + SMB_BYTES +
                        (size_t)(r_l * 36 + c_l) * 4) = pv;
                }
        }
        __syncthreads();
        if (Q == 0) {
            #pragma unroll
            for (int nt = 0; nt < 2; ++nt) {
                #pragma unroll
                for (int rh = 0; rh < 2; ++rh) {
                    const int r_l = wm * 16 + g + rh * 8;
                    const int c_l = wn * 16 + nt * 8 + q * 2;
                    float2 pv = *reinterpret_cast<const float2*>(
                        smem + SMB_BYTES + (size_t)(r_l * 36 + c_l) * 4);
                    const int row = m0 + r_l;
                    const int col = n0 + c_l;
                    float2 x2 = xv[nt * 2 + rh];
                    float v0 = tanhf(x2.x + acc[nt * 4 + rh * 2 + 0] + pv.x);
                    float v1 = tanhf(x2.y + acc[nt * 4 + rh * 2 + 1] + pv.y);
                    float2 ov; ov.x = v0; ov.y = v1;
                    *reinterpret_cast<float2*>(out_t + (size_t)row * LATENT + col) = ov;

                    __nv_bfloat16 h0 = __float2bfloat16(v0);
                    __nv_bfloat16 h1 = __float2bfloat16(v1);
                    __nv_bfloat162 hp; hp.x = h0; hp.y = h1;
                    __nv_bfloat162 lp;
                    lp.x = __float2bfloat16(v0 - __bfloat162float(h0));
                    lp.y = __float2bfloat16(v1 - __bfloat162float(h1));
                    const size_t ao = (size_t)row * KA + col;
                    *reinterpret_cast<__nv_bfloat162*>(aw + ao)        = hp;
                    *reinterpret_cast<__nv_bfloat162*>(aw + ao + 1024) = lp;
                }
            }
        }

        // ---- software grid barrier ----
        if (t + 1 < TT) {
            __threadfence();
            __syncthreads();
            if (tid == 0) {
                unsigned old = atomicAdd(&g_bar_count, 1u);
                if (old == (unsigned)(t * NCTA - 1)) {
                    g_bar_epoch = (unsigned)t;
                } else {
                    while (g_bar_epoch < (unsigned)t) { }
                    __threadfence();
                }
            }
            __syncthreads();
        }
    }
}

// ---------------------------------------------------------------------------
extern "C" void kernel_launch(void* const* d_in, const int* in_sizes, int n_in,
                              void* d_out, int out_size) {
    const float* x    = (const float*)d_in[0];   // [B, T, DIM]
    const float* W    = (const float*)d_in[1];   // [DIM+LATENT, LATENT]
    const float* bias = (const float*)d_in[2];   // [LATENT]
    float* out = (float*)d_out;                  // [T, B, LATENT]

    static int configured = 0;
    if (!configured) {
        cudaFuncSetAttribute(scan_kernel,
                             cudaFuncAttributeMaxDynamicSharedMemorySize, SMEM_SCAN);
        cudaFuncSetAttribute(gemm1_mma_kernel,
                             cudaFuncAttributeMaxDynamicSharedMemorySize, G1_SMEM);
        configured = 1;
    }

    // 0) weight + input splits
    prep_wh_kernel<<<dim3(32, 32), dim3(32, 8)>>>(W);
    prep_bx_kernel<<<dim3(32, 8),  dim3(32, 8)>>>(W);
    prep_x_kernel<<<(BB * TT * DIMK / 4) / 256, 256>>>(x);

    // 1) xw + bias staged into out[t, b, :] (tensor cores)
    gemm1_mma_kernel<<<BB * TT / 64, 256, G1_SMEM>>>(bias, out);

    // 2) t = 0 (+ barrier state reset)
    tanh0_kernel<<<(BB * LATENT) / 256, 256>>>(out);

    // 3) persistent tensor-core scan for t = 1..511
    scan_kernel<<<NCTA, 256, SMEM_SCAN>>>(out);
}

// round 7
// speedup vs baseline: 6.3656x; 1.4570x over previous
#include <cuda_runtime.h>
#include <cuda_bf16.h>
#include <math.h>
#include <stdint.h>

#define DIMK   256
#define LATENT 1024
#define BB     128
#define TT     512
#define KA     2048          // A' (scan) columns: [hi | lo]
#define KB     2048          // B' (scan) columns: [hi | lo]
#define NCTA   128

// ---------------------------------------------------------------------------
// Scratch (__device__ globals — no allocations allowed)
// ---------------------------------------------------------------------------
__device__ __nv_bfloat16 g_B[LATENT * KB];              // scan B' = WhT split [n][hi1024|lo1024]
__device__ __nv_bfloat16 g_A2[2][BB * KA];              // scan A' ping-pong [m][hi1024|lo1024]
__device__ __nv_bfloat16 g_X[(size_t)BB * TT * 512];    // gemm1 A' = x split [r][hi256|lo256]
__device__ __nv_bfloat16 g_BX[LATENT * 512];            // gemm1 B' = WxT split [n][hi256|lo256]
__device__ unsigned g_bar_count;

__device__ __forceinline__ uint32_t smem_u32(const void* p) {
    uint32_t a;
    asm("{ .reg .u64 t; cvta.to.shared.u64 t, %1; cvt.u32.u64 %0, t; }" : "=r"(a) : "l"(p));
    return a;
}
__device__ __forceinline__ void cp16(uint32_t dst, const void* src) {
    asm volatile("cp.async.cg.shared.global [%0], [%1], 16;" :: "r"(dst), "l"(src));
}
#define CP_COMMIT() asm volatile("cp.async.commit_group;")
#define CP_WAIT(n)  asm volatile("cp.async.wait_group %0;" :: "n"(n))
#define BARQ(id)    asm volatile("bar.sync %0, 128;" :: "r"(id) : "memory")

#define LDSM4(r0, r1, r2, r3, addr) \
    asm volatile("ldmatrix.sync.aligned.m8n8.x4.shared.b16 {%0,%1,%2,%3}, [%4];" \
                 : "=r"(r0), "=r"(r1), "=r"(r2), "=r"(r3) : "r"(addr))
#define MMA16816(d, a0, a1, a2, a3, b0, b1) \
    asm volatile("mma.sync.aligned.m16n8k16.row.col.f32.bf16.bf16.f32 " \
                 "{%0,%1,%2,%3}, {%4,%5,%6,%7}, {%8,%9}, {%0,%1,%2,%3};" \
                 : "+f"((d)[0]), "+f"((d)[1]), "+f"((d)[2]), "+f"((d)[3]) \
                 : "r"(a0), "r"(a1), "r"(a2), "r"(a3), "r"(b0), "r"(b1))

// ---------------------------------------------------------------------------
// prep: Wh[k][n] -> g_B[n][k]=hi, g_B[n][1024+k]=lo
// ---------------------------------------------------------------------------
__global__ void prep_wh_kernel(const float* __restrict__ W) {
    const float* Wh = W + (size_t)DIMK * LATENT;
    __shared__ float tile[32][33];
    int bx = blockIdx.x * 32;   // n base
    int by = blockIdx.y * 32;   // k base
    int tx = threadIdx.x, ty = threadIdx.y;
    #pragma unroll
    for (int i = ty; i < 32; i += 8)
        tile[i][tx] = Wh[(size_t)(by + i) * LATENT + bx + tx];
    __syncthreads();
    #pragma unroll
    for (int i = ty; i < 32; i += 8) {
        float v = tile[tx][i];
        size_t o = (size_t)(bx + i) * KB + by + tx;
        __nv_bfloat16 h = __float2bfloat16(v);
        g_B[o]        = h;
        g_B[o + 1024] = __float2bfloat16(v - __bfloat162float(h));
    }
}

// ---------------------------------------------------------------------------
// prep: Wx[k][n] (k<256) -> g_BX[n][k]=hi, [n][256+k]=lo
// ---------------------------------------------------------------------------
__global__ void prep_bx_kernel(const float* __restrict__ W) {
    __shared__ float tile[32][33];
    int bx = blockIdx.x * 32;   // n base
    int by = blockIdx.y * 32;   // k base (0..224)
    int tx = threadIdx.x, ty = threadIdx.y;
    #pragma unroll
    for (int i = ty; i < 32; i += 8)
        tile[i][tx] = W[(size_t)(by + i) * LATENT + bx + tx];
    __syncthreads();
    #pragma unroll
    for (int i = ty; i < 32; i += 8) {
        float v = tile[tx][i];                       // Wx[k=by+tx][n=bx+i]
        size_t o = (size_t)(bx + i) * 512 + by + tx;
        __nv_bfloat16 h = __float2bfloat16(v);
        g_BX[o]       = h;
        g_BX[o + 256] = __float2bfloat16(v - __bfloat162float(h));
    }
}

// ---------------------------------------------------------------------------
// prep: x[r][d] fp32 -> g_X[r][d]=hi, g_X[r][256+d]=lo  (r = b*T + t)
// ---------------------------------------------------------------------------
__global__ void prep_x_kernel(const float* __restrict__ x) {
    size_t idx = (size_t)blockIdx.x * 256 + threadIdx.x;
    size_t e = idx * 4;
    size_t r = e >> 8;
    int d = (int)(e & 255);
    float4 v = *reinterpret_cast<const float4*>(x + e);
    __nv_bfloat16 h0 = __float2bfloat16(v.x), h1 = __float2bfloat16(v.y);
    __nv_bfloat16 h2 = __float2bfloat16(v.z), h3 = __float2bfloat16(v.w);
    __nv_bfloat162 hp0; hp0.x = h0; hp0.y = h1;
    __nv_bfloat162 hp1; hp1.x = h2; hp1.y = h3;
    __nv_bfloat162 lp0, lp1;
    lp0.x = __float2bfloat16(v.x - __bfloat162float(h0));
    lp0.y = __float2bfloat16(v.y - __bfloat162float(h1));
    lp1.x = __float2bfloat16(v.z - __bfloat162float(h2));
    lp1.y = __float2bfloat16(v.w - __bfloat162float(h3));
    size_t o = r * 512 + d;
    *reinterpret_cast<__nv_bfloat162*>(&g_X[o + 0])   = hp0;
    *reinterpret_cast<__nv_bfloat162*>(&g_X[o + 2])   = hp1;
    *reinterpret_cast<__nv_bfloat162*>(&g_X[o + 256]) = lp0;
    *reinterpret_cast<__nv_bfloat162*>(&g_X[o + 258]) = lp1;
}

// ---------------------------------------------------------------------------
// GEMM1 (tensor): out[t,b,:] = x @ Wx + b (unchanged from round 6; 375us)
// ---------------------------------------------------------------------------
#define G1_SMB   65536
#define G1_SMEM  (65536 + 2 * 16384)

__global__ void __launch_bounds__(256, 2)
gemm1_mma_kernel(const float* __restrict__ bias, float* __restrict__ out) {
    extern __shared__ char smem[];
    const uint32_t smA = smem_u32(smem);
    const uint32_t smB = smA + G1_SMB;
    const int tid = threadIdx.x;
    const int lid = tid & 31;
    const int wid = tid >> 5;
    const int r0 = blockIdx.x * 64;

    {
        const __nv_bfloat16* gA = g_X + (size_t)r0 * 512;
        #pragma unroll
        for (int j = 0; j < 16; ++j) {
            int ci = tid + j * 256;
            int ch = ci >> 10;
            int rem = ci & 1023;
            int rw = rem >> 4;
            int cc = rem & 15;
            cp16(smA + ch * 16384 + rw * 256 + (((cc ^ (rw & 15))) << 4),
                 gA + (size_t)rw * 512 + ch * 128 + cc * 8);
        }
        CP_COMMIT();
    }
    {
        #pragma unroll
        for (int j = 0; j < 4; ++j) {
            int ci = tid + j * 256;
            int rw = ci >> 4;
            int cc = ci & 15;
            cp16(smB + rw * 256 + (((cc ^ (rw & 15))) << 4),
                 g_BX + (size_t)rw * 512 + cc * 8);
        }
        CP_COMMIT();
    }

    const int wm = wid & 1;
    const int wn = wid >> 1;
    const int a_row0 = wm * 32 + (lid & 15);
    const int a_row1 = a_row0 + 16;
    const int a_kh   = (lid >> 4) & 1;
    const int b_row  = wn * 16 + (((lid >> 4) & 1) << 3) + (lid & 7);
    const int b_kh   = (lid >> 3) & 1;
    const int a_swz0 = a_row0 & 15, a_swz1 = a_row1 & 15, b_swz = b_row & 15;
    const int g8 = lid >> 2;
    const int q  = lid & 3;

    float acc[4][4];

    #pragma unroll 1
    for (int gg = 0; gg < 96; ++gg) {
        const int nt = gg / 6;
        const int c  = gg % 6;

        if (gg + 1 < 96) {
            const int nt2 = (gg + 1) / 6;
            const int c2  = (gg + 1) % 6;
            const int cb  = (c2 & 3) * 128;
            uint32_t dst = smB + ((gg + 1) & 1) * 16384;
            const __nv_bfloat16* gBn = g_BX + (size_t)(nt2 * 64) * 512;
            #pragma unroll
            for (int j = 0; j < 4; ++j) {
                int ci = tid + j * 256;
                int rw = ci >> 4;
                int cc = ci & 15;
                cp16(dst + rw * 256 + (((cc ^ (rw & 15))) << 4),
                     gBn + (size_t)rw * 512 + cb + cc * 8);
            }
            CP_COMMIT();
            CP_WAIT(1);
        } else {
            CP_WAIT(0);
        }
        __syncthreads();

        if (c == 0) {
            #pragma unroll
            for (int i = 0; i < 4; ++i)
                #pragma unroll
                for (int j = 0; j < 4; ++j) acc[i][j] = 0.f;
        }

        const int ach = (c < 2) ? c : c - 2;
        const uint32_t aR0 = smA + ach * 16384 + a_row0 * 256;
        const uint32_t aR1 = smA + ach * 16384 + a_row1 * 256;
        const uint32_t bR  = smB + (gg & 1) * 16384 + b_row * 256;

        #pragma unroll
        for (int s = 0; s < 8; ++s) {
            uint32_t A0, A1, A2, A3, C0, C1, C2, C3, B0, B1, B2, B3;
            LDSM4(A0, A1, A2, A3, aR0 + (((2 * s + a_kh) ^ a_swz0) << 4));
            LDSM4(C0, C1, C2, C3, aR1 + (((2 * s + a_kh) ^ a_swz1) << 4));
            LDSM4(B0, B1, B2, B3, bR  + (((2 * s + b_kh) ^ b_swz) << 4));
            MMA16816(acc[0], A0, A1, A2, A3, B0, B1);
            MMA16816(acc[1], A0, A1, A2, A3, B2, B3);
            MMA16816(acc[2], C0, C1, C2, C3, B0, B1);
            MMA16816(acc[3], C0, C1, C2, C3, B2, B3);
        }

        if (c == 5) {
            const int n0 = nt * 64;
            #pragma unroll
            for (int f = 0; f < 2; ++f) {
                #pragma unroll
                for (int ntf = 0; ntf < 2; ++ntf) {
                    const int col = n0 + wn * 16 + ntf * 8 + q * 2;
                    float2 bv = *reinterpret_cast<const float2*>(bias + col);
                    #pragma unroll
                    for (int rh = 0; rh < 2; ++rh) {
                        const int r = r0 + wm * 32 + f * 16 + g8 + rh * 8;
                        const int bi = r >> 9;
                        const int ti = r & (TT - 1);
                        float2 o;
                        o.x = acc[f * 2 + ntf][rh * 2 + 0] + bv.x;
                        o.y = acc[f * 2 + ntf][rh * 2 + 1] + bv.y;
                        *reinterpret_cast<float2*>(
                            &out[((size_t)ti * BB + bi) * LATENT + col]) = o;
                    }
                }
            }
        }
        __syncthreads();
    }
}

// ---------------------------------------------------------------------------
// t = 0: out[0] = tanh(out[0]); split h0 into g_A2[0]; reset barrier counter
// ---------------------------------------------------------------------------
__global__ void tanh0_kernel(float* __restrict__ out0) {
    int i = blockIdx.x * blockDim.x + threadIdx.x;
    if (i == 0) { g_bar_count = 0; }
    int m = i >> 10;
    int k = i & 1023;
    float v = tanhf(out0[i]);
    out0[i] = v;
    __nv_bfloat16 h = __float2bfloat16(v);
    size_t o = (size_t)m * KA + k;
    g_A2[0][o]        = h;
    g_A2[0][o + 1024] = __float2bfloat16(v - __bfloat162float(h));
}

// ---------------------------------------------------------------------------
// Persistent scan: 128 CTAs (4m x 32n tiles of 32x32), 256 threads = 2 quads.
// Per k-chunk kk: acc1 += Ahi*Bhi, acc2 += Ahi*Blo, acc3 += Alo*Bhi (B_hi reused).
// B' resident (hi+lo, 128KB). A: 3-deep 16KB-slot pipeline per quad, 1 bar/iter.
// Split-K: quad0 kk 0-3, quad1 kk 4-7; partial exchange in reused A smem;
// epilogue split over all 256 threads; grid barrier = RED + count poll.
// ---------------------------------------------------------------------------
#define SCAN_SMB  131072                      // B: 16 chunks x 8KB (hi at k*8KB, lo at 64KB + k*8KB)
#define SMEM_SCAN (SCAN_SMB + 6 * 16384)      // + 2 quads x 3 slots x 16KB = 229376

__global__ void __launch_bounds__(256, 1)
scan_kernel(float* __restrict__ out) {
    extern __shared__ char smem[];
    const int tid = threadIdx.x;
    const int lid = tid & 31;
    const int wid = tid >> 5;
    const int Q = wid >> 2;             // quad id (k-split)
    const int qwid = wid & 3;
    const int qtid = tid & 127;
    const int bid = blockIdx.x;
    const int m0 = (bid & 3) * 32;
    const int n0 = (bid >> 2) * 32;

    const uint32_t smB = smem_u32(smem);
    const uint32_t smA = smB + SCAN_SMB;
    const uint32_t qstage = smA + Q * 49152;   // 3 slots x 16KB (hi 8KB + lo 8KB)

    // ---- resident B': 8192 cp16, 32/thread ----
    {
        const __nv_bfloat16* gB = g_B + (size_t)n0 * KB;
        #pragma unroll
        for (int j = 0; j < 32; ++j) {
            int ci = tid + j * 256;
            int half = ci >> 12;
            int rem = ci & 4095;
            int ch = rem >> 9;
            int rw = (rem >> 4) & 31;
            int cc = rem & 15;
            cp16(smB + half * 65536 + ch * 8192 + rw * 256 + (((cc ^ (rw & 15))) << 4),
                 gB + (size_t)rw * KB + half * 1024 + ch * 128 + cc * 8);
        }
        CP_COMMIT();
        CP_WAIT(0);
        __syncthreads();
    }

    // ---- lane geometry ----
    const int wm = qwid & 1;
    const int wn = qwid >> 1;
    const int a_row = wm * 16 + (lid & 15);
    const int a_kh  = (lid >> 4) & 1;
    const int b_row = wn * 16 + (((lid >> 4) & 1) << 3) + (lid & 7);
    const int b_kh  = (lid >> 3) & 1;
    const int a_swz = a_row & 15;
    const int b_swz = b_row & 15;
    const int kbase = Q * 4;

    // A staging coords: 8 x 16B per thread per k-iter (hi chunk + lo chunk)
    int s_half[8], s_rw[8], s_cc[8];
    #pragma unroll
    for (int j = 0; j < 8; ++j) {
        int ci = qtid + j * 128;          // 0..1023
        s_half[j] = ci >> 9;              // 0 = hi, 1 = lo
        int rem = ci & 511;
        s_rw[j] = rem >> 4;
        s_cc[j] = rem & 15;
    }

    // epilogue mapping: each thread owns 4 consecutive cols of one row
    const int e_row = tid >> 3;           // 0..31
    const int e_cg  = (tid & 7) * 4;      // 0..28

    for (int t = 1; t < TT; ++t) {
        const int rp = (t - 1) & 1;
        const __nv_bfloat16* gA = g_A2[rp] + (size_t)m0 * KA;
        __nv_bfloat16* aw = g_A2[rp ^ 1];
        float* out_t = out + (size_t)t * BB * LATENT;

        // ---- stage k-iters 0,1 into slots 0,1 ----
        #pragma unroll
        for (int p = 0; p < 2; ++p) {
            const int kk = kbase + p;
            uint32_t dst = qstage + p * 16384;
            #pragma unroll
            for (int j = 0; j < 8; ++j)
                cp16(dst + s_half[j] * 8192 + s_rw[j] * 256 + (((s_cc[j] ^ (s_rw[j] & 15))) << 4),
                     gA + (size_t)s_rw[j] * KA + s_half[j] * 1024 + kk * 128 + s_cc[j] * 8);
            CP_COMMIT();
        }

        // ---- xw prefetch (DRAM latency hidden under k-loop) ----
        float4 xv = *reinterpret_cast<const float4*>(
            out_t + (size_t)(m0 + e_row) * LATENT + n0 + e_cg);

        CP_WAIT(1);
        BARQ(Q + 1);

        float acc1[8] = {}, acc2[8] = {}, acc3[8] = {};

        #pragma unroll
        for (int i = 0; i < 4; ++i) {
            // stage iter i+2 into slot (i+2)%3 (freed slot; safe after prev BARQ)
            if (i < 2) {
                const int kk = kbase + i + 2;
                uint32_t dst = qstage + ((i + 2) % 3) * 16384;
                #pragma unroll
                for (int j = 0; j < 8; ++j)
                    cp16(dst + s_half[j] * 8192 + s_rw[j] * 256 + (((s_cc[j] ^ (s_rw[j] & 15))) << 4),
                         gA + (size_t)s_rw[j] * KA + s_half[j] * 1024 + kk * 128 + s_cc[j] * 8);
                CP_COMMIT();
            }

            const int kk = kbase + i;
            const uint32_t slot = qstage + (i % 3) * 16384;
            const uint32_t aH = slot + a_row * 256;
            const uint32_t aL = slot + 8192 + a_row * 256;
            const uint32_t bH = smB + kk * 8192 + b_row * 256;
            const uint32_t bL = smB + 65536 + kk * 8192 + b_row * 256;

            #pragma unroll
            for (int s = 0; s < 8; ++s) {
                const uint32_t ak = ((2 * s + a_kh) ^ a_swz) << 4;
                const uint32_t bk = ((2 * s + b_kh) ^ b_swz) << 4;
                uint32_t A0, A1, A2, A3, L0, L1, L2, L3;
                uint32_t B0, B1, B2, B3, D0, D1, D2, D3;
                LDSM4(A0, A1, A2, A3, aH + ak);
                LDSM4(B0, B1, B2, B3, bH + bk);
                MMA16816(acc1,     A0, A1, A2, A3, B0, B1);
                MMA16816(acc1 + 4, A0, A1, A2, A3, B2, B3);
                LDSM4(D0, D1, D2, D3, bL + bk);
                MMA16816(acc2,     A0, A1, A2, A3, D0, D1);
                MMA16816(acc2 + 4, A0, A1, A2, A3, D2, D3);
                LDSM4(L0, L1, L2, L3, aL + ak);
                MMA16816(acc3,     L0, L1, L2, L3, B0, B1);
                MMA16816(acc3 + 4, L0, L1, L2, L3, B2, B3);
            }

            if (i == 0 || i == 1) { CP_WAIT(1); }
            else if (i == 2)      { CP_WAIT(0); }
            if (i < 3) BARQ(Q + 1);
        }

        // ---- partial exchange (reuse A-stage smem after full sync) ----
        __syncthreads();
        {
            char* pbase = smem + SCAN_SMB + Q * 4096;
            #pragma unroll
            for (int nt = 0; nt < 2; ++nt)
                #pragma unroll
                for (int rh = 0; rh < 2; ++rh) {
                    const int r_l = wm * 16 + (lid >> 2) + rh * 8;
                    const int c_l = wn * 16 + nt * 8 + (lid & 3) * 2;
                    float2 pv;
                    pv.x = acc1[nt * 4 + rh * 2 + 0] + acc2[nt * 4 + rh * 2 + 0]
                         + acc3[nt * 4 + rh * 2 + 0];
                    pv.y = acc1[nt * 4 + rh * 2 + 1] + acc2[nt * 4 + rh * 2 + 1]
                         + acc3[nt * 4 + rh * 2 + 1];
                    *reinterpret_cast<float2*>(pbase + (size_t)(r_l * 32 + c_l) * 4) = pv;
                }
        }
        __syncthreads();

        // ---- epilogue: all 256 threads, 4 outputs each ----
        {
            const float4 p0 = *reinterpret_cast<const float4*>(
                smem + SCAN_SMB + (size_t)(e_row * 32 + e_cg) * 4);
            const float4 p1 = *reinterpret_cast<const float4*>(
                smem + SCAN_SMB + 4096 + (size_t)(e_row * 32 + e_cg) * 4);
            float4 r;
            r.x = tanhf(xv.x + p0.x + p1.x);
            r.y = tanhf(xv.y + p0.y + p1.y);
            r.z = tanhf(xv.z + p0.z + p1.z);
            r.w = tanhf(xv.w + p0.w + p1.w);
            *reinterpret_cast<float4*>(
                out_t + (size_t)(m0 + e_row) * LATENT + n0 + e_cg) = r;

            __nv_bfloat16 h0 = __float2bfloat16(r.x);
            __nv_bfloat16 h1 = __float2bfloat16(r.y);
            __nv_bfloat16 h2 = __float2bfloat16(r.z);
            __nv_bfloat16 h3 = __float2bfloat16(r.w);
            __nv_bfloat162 hp0; hp0.x = h0; hp0.y = h1;
            __nv_bfloat162 hp1; hp1.x = h2; hp1.y = h3;
            __nv_bfloat162 lp0, lp1;
            lp0.x = __float2bfloat16(r.x - __bfloat162float(h0));
            lp0.y = __float2bfloat16(r.y - __bfloat162float(h1));
            lp1.x = __float2bfloat16(r.z - __bfloat162float(h2));
            lp1.y = __float2bfloat16(r.w - __bfloat162float(h3));
            const size_t ao = (size_t)(m0 + e_row) * KA + n0 + e_cg;
            *reinterpret_cast<__nv_bfloat162*>(aw + ao + 0)    = hp0;
            *reinterpret_cast<__nv_bfloat162*>(aw + ao + 2)    = hp1;
            *reinterpret_cast<__nv_bfloat162*>(aw + ao + 1024) = lp0;
            *reinterpret_cast<__nv_bfloat162*>(aw + ao + 1026) = lp1;
        }

        // ---- grid barrier: RED + all-CTA count poll (no releaser hop) ----
        if (t + 1 < TT) {
            __threadfence();
            __syncthreads();
            if (tid == 0) {
                atomicAdd(&g_bar_count, 1u);
                const unsigned target = (unsigned)t * NCTA;
                while (*(volatile unsigned*)&g_bar_count < target) { }
            }
            __syncthreads();
        }
    }
}

// ---------------------------------------------------------------------------
extern "C" void kernel_launch(void* const* d_in, const int* in_sizes, int n_in,
                              void* d_out, int out_size) {
    const float* x    = (const float*)d_in[0];   // [B, T, DIM]
    const float* W    = (const float*)d_in[1];   // [DIM+LATENT, LATENT]
    const float* bias = (const float*)d_in[2];   // [LATENT]
    float* out = (float*)d_out;                  // [T, B, LATENT]

    static int configured = 0;
    if (!configured) {
        cudaFuncSetAttribute(scan_kernel,
                             cudaFuncAttributeMaxDynamicSharedMemorySize, SMEM_SCAN);
        cudaFuncSetAttribute(gemm1_mma_kernel,
                             cudaFuncAttributeMaxDynamicSharedMemorySize, G1_SMEM);
        configured = 1;
    }

    // 0) weight + input splits
    prep_wh_kernel<<<dim3(32, 32), dim3(32, 8)>>>(W);
    prep_bx_kernel<<<dim3(32, 8),  dim3(32, 8)>>>(W);
    prep_x_kernel<<<(BB * TT * DIMK / 4) / 256, 256>>>(x);

    // 1) xw + bias staged into out[t, b, :] (tensor cores)
    gemm1_mma_kernel<<<BB * TT / 64, 256, G1_SMEM>>>(bias, out);

    // 2) t = 0 (+ barrier counter reset)
    tanh0_kernel<<<(BB * LATENT) / 256, 256>>>(out);

    // 3) persistent tensor-core scan for t = 1..511
    scan_kernel<<<NCTA, 256, SMEM_SCAN>>>(out);
}